// round 9
// baseline (speedup 1.0000x reference)
#include <cuda_runtime.h>
#include <cuda_bf16.h>
#include <cstdint>

// Problem constants (fixed shapes)
#define BATCH 2
#define CDIM 128
#define NPIX 65536          // 256*256
#define LAST0 64512         // (chunks-1)*M
#define NROWBLK 4096        // NPIX/16
#define NTILES 1024         // 2 batches x 512 row-tiles of 128
#define SCALE_L2 20.6099075f   // 1/(0.07 * ln2)
#define LN2F 0.6931471805599453f

typedef unsigned long long u64;

// ---------------- scratch (device globals: no allocations allowed) ----------
__device__ uint4    g_Apack[BATCH * NROWBLK * 8 * 32];   // 33.5 MB, bf16 mma A fragments
__device__ uint4    g_Bpack[BATCH * 16 * 1024];          // 512 KB: [b][it][(nb*4+s2)*32+lane]
__device__ float    g_inv2[BATCH * NPIX];
__device__ float    g_posl2[BATCH * NPIX];               // pos logit in log2 domain
__device__ double   g_acc;
__device__ unsigned g_tile;                              // persistent work queue

// ---------------- helpers ----------------
__device__ __forceinline__ unsigned pack2(float lo, float hi) {
    __nv_bfloat162 h = __floats2bfloat162_rn(lo, hi);
    return *reinterpret_cast<unsigned*>(&h);
}
__device__ __forceinline__ u64 pk(float lo, float hi) {
    u64 r; asm("mov.b64 %0,{%1,%2};" : "=l"(r) : "f"(lo), "f"(hi)); return r;
}
__device__ __forceinline__ u64 bc(float x) {
    u64 r; asm("mov.b64 %0,{%1,%1};" : "=l"(r) : "f"(x)); return r;
}
__device__ __forceinline__ u64 fma2(u64 a, u64 b, u64 c) {
    u64 d; asm("fma.rn.f32x2 %0,%1,%2,%3;" : "=l"(d) : "l"(a), "l"(b), "l"(c)); return d;
}
__device__ __forceinline__ u64 add2(u64 a, u64 b) {
    u64 d; asm("add.rn.f32x2 %0,%1,%2;" : "=l"(d) : "l"(a), "l"(b)); return d;
}
__device__ __forceinline__ u64 sub2(u64 a, u64 b) {
    u64 d; asm("sub.rn.f32x2 %0,%1,%2;" : "=l"(d) : "l"(a), "l"(b)); return d;
}
// scalar exp2 (pos only). Exact at x==0.
__device__ __forceinline__ float exp2p(float x) {
    int   i = __float2int_rn(x);
    float f = x - (float)i;
    float p = 9.6181291076e-3f;
    p = fmaf(p, f, 5.5504108664e-2f);
    p = fmaf(p, f, 2.4022650696e-1f);
    p = fmaf(p, f, 6.9314718056e-1f);
    p = fmaf(p, f, 1.0f);
    return __int_as_float(__float_as_int(p) + (i << 23));
}

#define CP16(dst, src) asm volatile("cp.async.ca.shared.global [%0],[%1],16;\n" :: "r"(dst), "l"(src))
#define CPCOMMIT()     asm volatile("cp.async.commit_group;\n")
#define CPWAIT0()      asm volatile("cp.async.wait_group 0;\n")

#define MMA_BF16(c0, c1, c2, c3, av, b0, b1)                               \
    asm volatile(                                                           \
        "mma.sync.aligned.m16n8k16.row.col.f32.bf16.bf16.f32 "             \
        "{%0,%1,%2,%3}, {%4,%5,%6,%7}, {%8,%9}, {%0,%1,%2,%3};\n"          \
        : "+f"(c0), "+f"(c1), "+f"(c2), "+f"(c3)                            \
        : "r"((av).x), "r"((av).y), "r"((av).z), "r"((av).w),               \
          "r"(b0), "r"(b1))

// packed exp2 accumulate: sep += exp2(P) elementwise (deg-3 Taylor, exact at 0)
#define EXP2ACC(sep, P) do {                                                \
    u64 t  = add2(P, MAG);                                                  \
    u64 ii = sub2(t, MAG);                                                  \
    u64 f  = sub2(P, ii);                                                   \
    u64 p  = fma2(C3, f, C2);                                               \
    p = fma2(p, f, C1); p = fma2(p, f, ONE);                                \
    unsigned t0, t1, q0, q1;                                                \
    asm("mov.b64 {%0,%1},%2;" : "=r"(t0), "=r"(t1) : "l"(t));               \
    asm("mov.b64 {%0,%1},%2;" : "=r"(q0), "=r"(q1) : "l"(p));               \
    q0 += t0 << 23; q1 += t1 << 23;                                         \
    u64 e; asm("mov.b64 %0,{%1,%2};" : "=l"(e) : "r"(q0), "r"(q1));         \
    sep = add2(sep, e);                                                     \
} while (0)

// epilogue directly on chain accumulators (previous nb's completed results)
#define EPILOGUE() do {                                                     \
    u64 P0 = pk((lr0 != lcp.x) ? cA0 : 0.f, (lr0 != lcp.y) ? cA1 : 0.f);    \
    u64 P1 = pk((lr1 != lcp.x) ? cA2 : 0.f, (lr1 != lcp.y) ? cA3 : 0.f);    \
    u64 P2 = pk((lr2 != lcp.x) ? cB0 : 0.f, (lr2 != lcp.y) ? cB1 : 0.f);    \
    u64 P3 = pk((lr3 != lcp.x) ? cB2 : 0.f, (lr3 != lcp.y) ? cB3 : 0.f);    \
    sxp = add2(sxp, add2(add2(P0, P1), add2(P2, P3)));                      \
    EXP2ACC(sep0, P0);                                                      \
    EXP2ACC(sep1, P1);                                                      \
    EXP2ACC(sep2, P2);                                                      \
    EXP2ACC(sep3, P3);                                                      \
} while (0)

// ---------------- kernel 1: normalize z1/z2, compute pos (fp32), pack A fragments ----
__global__ void __launch_bounds__(256) k_norm_pack(const float* __restrict__ z1,
                                                   const float* __restrict__ z2) {
    if (blockIdx.x == 0 && blockIdx.y == 0 && threadIdx.x == 0) {
        g_acc = 0.0;
        g_tile = 0u;
    }
    const int b  = blockIdx.y;
    const int p0 = blockIdx.x * 32;
    const int tx = threadIdx.x & 31;   // pixel within tile
    const int ty = threadIdx.x >> 5;   // channel group

    __shared__ float s1[128][33];
    __shared__ float red[3][8][32];
    __shared__ float invsm[32];

    const float* z1b = z1 + (size_t)b * CDIM * NPIX + p0;
    const float* z2b = z2 + (size_t)b * CDIM * NPIX + p0;

    float ss1 = 0.f, ss2 = 0.f, dt = 0.f;
#pragma unroll
    for (int j = 0; j < 16; j++) {
        int c = ty * 16 + j;
        float v1 = z1b[(size_t)c * NPIX + tx];
        float v2 = z2b[(size_t)c * NPIX + tx];
        ss1 = fmaf(v1, v1, ss1);
        ss2 = fmaf(v2, v2, ss2);
        dt  = fmaf(v1, v2, dt);
        s1[c][tx] = v1;
    }
    red[0][ty][tx] = ss1; red[1][ty][tx] = ss2; red[2][ty][tx] = dt;
    __syncthreads();

    if (ty == 0) {
        float a = 0.f, bb = 0.f, d = 0.f;
#pragma unroll
        for (int j = 0; j < 8; j++) { a += red[0][j][tx]; bb += red[1][j][tx]; d += red[2][j][tx]; }
        float inv1 = 1.f / fmaxf(sqrtf(a),  1e-12f);
        float inv2 = 1.f / fmaxf(sqrtf(bb), 1e-12f);
        invsm[tx] = inv1;
        g_inv2 [b * NPIX + p0 + tx] = inv2;
        g_posl2[b * NPIX + p0 + tx] = d * inv1 * inv2 * SCALE_L2;  // pos in log2 domain
    }
    __syncthreads();

    // Pack A into mma fragment order
#pragma unroll
    for (int q = 0; q < 2; q++) {
        int wi   = threadIdx.x + q * 256;
        int rbl  = wi >> 8;
        int rem  = wi & 255;
        int s    = rem >> 5;
        int lane = rem & 31;
        int gid  = lane >> 2, tig = lane & 3;
        int pl   = rbl * 16 + gid;
        int k0   = s * 16 + tig * 2;
        float i1 = invsm[pl], i2 = invsm[pl + 8];
        uint4 o;
        o.x = pack2(s1[k0    ][pl]     * i1, s1[k0 + 1][pl]     * i1);
        o.y = pack2(s1[k0    ][pl + 8] * i2, s1[k0 + 1][pl + 8] * i2);
        o.z = pack2(s1[k0 + 8][pl]     * i1, s1[k0 + 9][pl]     * i1);
        o.w = pack2(s1[k0 + 8][pl + 8] * i2, s1[k0 + 9][pl + 8] * i2);
        int rb = blockIdx.x * 2 + rbl;
        g_Apack[((b * NROWBLK + rb) * 8 + s) * 32 + lane] = o;
    }
}

// ---------------- kernel 2: pack B fragments as uint4 (2 k-steps per entry) --------
__global__ void k_packB(const float* __restrict__ z2) {
    int g = blockIdx.x * 256 + threadIdx.x;       // 0..32767
    int b   = g >> 14;
    int r   = g & 16383;
    int it  = r >> 10;
    int idx = r & 1023;
    int nb  = idx >> 7;
    int s2  = (idx >> 5) & 3;
    int lane = idx & 31;
    int gid = lane >> 2, tig = lane & 3;
    int n  = nb * 8 + gid;
    int pq = LAST0 + it * 64 + n;
    float inv = g_inv2[b * NPIX + pq] * SCALE_L2;
    const float* zp = z2 + (size_t)b * CDIM * NPIX + pq;
    int k0 = s2 * 32 + tig * 2;
    uint4 o;
    o.x = pack2(zp[(size_t)(k0     ) * NPIX] * inv, zp[(size_t)(k0 +  1) * NPIX] * inv);
    o.y = pack2(zp[(size_t)(k0 +  8) * NPIX] * inv, zp[(size_t)(k0 +  9) * NPIX] * inv);
    o.z = pack2(zp[(size_t)(k0 + 16) * NPIX] * inv, zp[(size_t)(k0 + 17) * NPIX] * inv);
    o.w = pack2(zp[(size_t)(k0 + 24) * NPIX] * inv, zp[(size_t)(k0 + 25) * NPIX] * inv);
    g_Bpack[g] = o;
}

// ---------------- kernel 3: persistent bf16 GEMM + fused epilogue -------------------
// 592 blocks x 128 threads, 4 blocks/SM. Tiles (b, 128 rows) from an atomic queue.
__global__ void __launch_bounds__(128, 4) k_main(const int* __restrict__ labels) {
    const int tid  = threadIdx.x;      // 0..127
    const int w    = tid >> 5;         // 0..3
    const int lane = tid & 31;
    const int gid  = lane >> 2, tig = lane & 3;

    __shared__ uint4    Bsm[2][1024];   // double-buffered 16KB B tiles
    __shared__ int      labsm[1024];
    __shared__ float    warpsum[4];
    __shared__ unsigned s_tile;

    // packed constants
    const u64 MAG = bc(12582912.0f);   // 1.5 * 2^23
    const u64 C3 = bc(5.5504108664e-2f);
    const u64 C2 = bc(2.4022650696e-1f);
    const u64 C1 = bc(6.9314718056e-1f);
    const u64 ONE = bc(1.0f);

    for (;;) {
        if (tid == 0) s_tile = atomicAdd(&g_tile, 1u);
        __syncthreads();
        const unsigned t = s_tile;
        if (t >= NTILES) break;
        const int b    = t >> 9;
        const int tloc = t & 511;
        const int row0 = tloc * 128;

        // labels of last chunk -> shared (visibility covered by it0's barrier)
        {
            const uint4* lp = (const uint4*)(labels + b * NPIX + LAST0);
            ((uint4*)labsm)[tid]       = lp[tid];
            ((uint4*)labsm)[tid + 128] = lp[tid + 128];
        }

        // A fragments for this warp's 32 rows (2 rowblocks): 16 x uint4
        const int rb0 = tloc * 8 + w * 2;
        uint4 a0[8], a1[8];
        const uint4* Ap = g_Apack + ((size_t)(b * NROWBLK + rb0) * 8) * 32 + lane;
#pragma unroll
        for (int s = 0; s < 8; s++) { a0[s] = Ap[s * 32]; a1[s] = Ap[256 + s * 32]; }

        const int r0  = row0 + w * 32 + gid;
        const int lr0 = labels[b * NPIX + r0];
        const int lr1 = labels[b * NPIX + r0 + 8];
        const int lr2 = labels[b * NPIX + r0 + 16];
        const int lr3 = labels[b * NPIX + r0 + 24];

        u64 sxp = 0;                                   // warp-global sum of masked logits
        u64 sep0 = 0, sep1 = 0, sep2 = 0, sep3 = 0;    // per-row-pair exp sums

        // 2 serial mma chains (one per rowblock), consumed one nb later
        float cA0=0.f,cA1=0.f,cA2=0.f,cA3=0.f;
        float cB0=0.f,cB1=0.f,cB2=0.f,cB3=0.f;
        int2  lcp = make_int2(0, 0);

        const uint4* Bp = g_Bpack + b * 16384;

        // prefetch tile 0 (1024 uint4 by 128 threads)
        {
            unsigned sd = (unsigned)__cvta_generic_to_shared(&Bsm[0][0]);
#pragma unroll
            for (int i = 0; i < 8; i++)
                CP16(sd + (tid + 128 * i) * 16, Bp + tid + 128 * i);
            CPCOMMIT();
        }

        for (int it = 0; it < 16; it++) {
            const int buf = it & 1;
            CPWAIT0();
            __syncthreads();   // data visible to all; all warps done with buf^1
            if (it < 15) {
                unsigned sd = (unsigned)__cvta_generic_to_shared(&Bsm[buf ^ 1][0]);
                const uint4* src = Bp + (it + 1) * 1024;
#pragma unroll
                for (int i = 0; i < 8; i++)
                    CP16(sd + (tid + 128 * i) * 16, src + tid + 128 * i);
                CPCOMMIT();
            }

            const uint4* Bb = &Bsm[buf][0];
#pragma unroll
            for (int nb = 0; nb < 8; nb++) {
                // (1) epilogue for previous nb (chains completed long ago)
                if (it + nb > 0) EPILOGUE();
                // (2) re-arm chains and issue this nb's 16 mmas
                cA0=0.f;cA1=0.f;cA2=0.f;cA3=0.f;
                cB0=0.f;cB1=0.f;cB2=0.f;cB3=0.f;
#pragma unroll
                for (int s2 = 0; s2 < 4; s2++) {
                    uint4 bf = Bb[(nb * 4 + s2) * 32 + lane];
                    MMA_BF16(cA0, cA1, cA2, cA3, a0[2 * s2],     bf.x, bf.y);
                    MMA_BF16(cB0, cB1, cB2, cB3, a1[2 * s2],     bf.x, bf.y);
                    MMA_BF16(cA0, cA1, cA2, cA3, a0[2 * s2 + 1], bf.z, bf.w);
                    MMA_BF16(cB0, cB1, cB2, cB3, a1[2 * s2 + 1], bf.z, bf.w);
                }
                // (3) capture this nb's column labels for next round's epilogue
                lcp = ((const int2*)labsm)[it * 32 + nb * 4 + tig];
            }
        }

        // drain: epilogue for the final nb
        EPILOGUE();

        // unpack packed accumulators
        float sa, sb;
        asm("mov.b64 {%0,%1},%2;" : "=f"(sa), "=f"(sb) : "l"(sxp));  float sxw = sa + sb;
        asm("mov.b64 {%0,%1},%2;" : "=f"(sa), "=f"(sb) : "l"(sep0)); float se0 = sa + sb;
        asm("mov.b64 {%0,%1},%2;" : "=f"(sa), "=f"(sb) : "l"(sep1)); float se1 = sa + sb;
        asm("mov.b64 {%0,%1},%2;" : "=f"(sa), "=f"(sb) : "l"(sep2)); float se2 = sa + sb;
        asm("mov.b64 {%0,%1},%2;" : "=f"(sa), "=f"(sb) : "l"(sep3)); float se3 = sa + sb;

        // per-row exp sums: reduce across the 4 lanes sharing each row
#pragma unroll
        for (int o = 1; o <= 2; o <<= 1) {
            se0 += __shfl_xor_sync(~0u, se0, o);
            se1 += __shfl_xor_sync(~0u, se1, o);
            se2 += __shfl_xor_sync(~0u, se2, o);
            se3 += __shfl_xor_sync(~0u, se3, o);
        }

        float v = 0.f;
        if (tig == 0) {
            float p0 = g_posl2[b * NPIX + r0];
            float p1 = g_posl2[b * NPIX + r0 + 8];
            float p2 = g_posl2[b * NPIX + r0 + 16];
            float p3 = g_posl2[b * NPIX + r0 + 24];
            float t0 = se0 + exp2p(p0);
            float t1 = se1 + exp2p(p1);
            float t2 = se2 + exp2p(p2);
            float t3 = se3 + exp2p(p3);
            v = (__log2f(t0) + __log2f(t1) + __log2f(t2) + __log2f(t3))
                - (p0 + p1 + p2 + p3) * (1.0f / 1025.0f);
        }
        v -= sxw * (1.0f / 1025.0f / 32.0f);   // spread warp-global sx over 32 lanes
#pragma unroll
        for (int o = 16; o; o >>= 1) v += __shfl_xor_sync(~0u, v, o);
        if (lane == 0) warpsum[w] = LN2F * v;
        __syncthreads();
        if (tid == 0) {
            float ts = warpsum[0] + warpsum[1] + warpsum[2] + warpsum[3];
            atomicAdd(&g_acc, (double)ts);
        }
        __syncthreads();   // warpsum consumed before next tile reuses it
    }
}

// ---------------- kernel 4: finalize ----------------
__global__ void k_finalize(float* out) {
    out[0] = (float)(g_acc / (double)(BATCH * NPIX));
}

// ---------------- launch ----------------
extern "C" void kernel_launch(void* const* d_in, const int* in_sizes, int n_in,
                              void* d_out, int out_size) {
    const float* z1     = (const float*)d_in[0];
    const float* z2     = (const float*)d_in[1];
    const int*   labels = (const int*)d_in[2];
    (void)in_sizes; (void)n_in; (void)out_size;

    dim3 g1(NPIX / 32, BATCH);
    k_norm_pack<<<g1, 256>>>(z1, z2);
    k_packB<<<128, 256>>>(z2);
    k_main<<<592, 128>>>(labels);
    k_finalize<<<1, 1>>>((float*)d_out);
}

// round 10
// speedup vs baseline: 1.0291x; 1.0291x over previous
#include <cuda_runtime.h>
#include <cuda_bf16.h>
#include <cstdint>

// Problem constants (fixed shapes)
#define BATCH 2
#define CDIM 128
#define NPIX 65536          // 256*256
#define LAST0 64512         // (chunks-1)*M
#define NROWBLK 4096        // NPIX/16
#define NTILES 1024         // 2 batches x 512 row-tiles of 128
#define SCALE_L2 20.6099075f   // 1/(0.07 * ln2)
#define LN2F 0.6931471805599453f

typedef unsigned long long u64;

// ---------------- scratch (device globals: no allocations allowed) ----------
__device__ uint4    g_Apack[BATCH * NROWBLK * 8 * 32];   // 33.5 MB, bf16 mma A fragments
__device__ uint4    g_Bpack[BATCH * 16 * 1024];          // 512 KB: [b][it][(nb*4+s2)*32+lane]
__device__ float    g_inv2[BATCH * NPIX];
__device__ float    g_posl2[BATCH * NPIX];               // pos logit in log2 domain
__device__ double   g_acc;
__device__ unsigned g_tile;                              // persistent work queue

// ---------------- helpers ----------------
__device__ __forceinline__ unsigned pack2(float lo, float hi) {
    __nv_bfloat162 h = __floats2bfloat162_rn(lo, hi);
    return *reinterpret_cast<unsigned*>(&h);
}
__device__ __forceinline__ u64 pk(float lo, float hi) {
    u64 r; asm("mov.b64 %0,{%1,%2};" : "=l"(r) : "f"(lo), "f"(hi)); return r;
}
__device__ __forceinline__ u64 bc(float x) {
    u64 r; asm("mov.b64 %0,{%1,%1};" : "=l"(r) : "f"(x)); return r;
}
__device__ __forceinline__ u64 fma2(u64 a, u64 b, u64 c) {
    u64 d; asm("fma.rn.f32x2 %0,%1,%2,%3;" : "=l"(d) : "l"(a), "l"(b), "l"(c)); return d;
}
__device__ __forceinline__ u64 add2(u64 a, u64 b) {
    u64 d; asm("add.rn.f32x2 %0,%1,%2;" : "=l"(d) : "l"(a), "l"(b)); return d;
}
__device__ __forceinline__ u64 sub2(u64 a, u64 b) {
    u64 d; asm("sub.rn.f32x2 %0,%1,%2;" : "=l"(d) : "l"(a), "l"(b)); return d;
}
// scalar exp2 (pos only). Exact at x==0.
__device__ __forceinline__ float exp2p(float x) {
    int   i = __float2int_rn(x);
    float f = x - (float)i;
    float p = 9.6181291076e-3f;
    p = fmaf(p, f, 5.5504108664e-2f);
    p = fmaf(p, f, 2.4022650696e-1f);
    p = fmaf(p, f, 6.9314718056e-1f);
    p = fmaf(p, f, 1.0f);
    return __int_as_float(__float_as_int(p) + (i << 23));
}

#define CP16(dst, src) asm volatile("cp.async.ca.shared.global [%0],[%1],16;\n" :: "r"(dst), "l"(src))
#define CPCOMMIT()     asm volatile("cp.async.commit_group;\n")
#define CPWAIT0()      asm volatile("cp.async.wait_group 0;\n")

#define MMA_BF16(c0, c1, c2, c3, av, b0, b1)                               \
    asm volatile(                                                           \
        "mma.sync.aligned.m16n8k16.row.col.f32.bf16.bf16.f32 "             \
        "{%0,%1,%2,%3}, {%4,%5,%6,%7}, {%8,%9}, {%0,%1,%2,%3};\n"          \
        : "+f"(c0), "+f"(c1), "+f"(c2), "+f"(c3)                            \
        : "r"((av).x), "r"((av).y), "r"((av).z), "r"((av).w),               \
          "r"(b0), "r"(b1))

// packed exp2 accumulate: sep += exp2(P) elementwise (deg-3 Taylor, exact at 0)
#define EXP2ACC(sep, P) do {                                                \
    u64 t  = add2(P, MAG);                                                  \
    u64 ii = sub2(t, MAG);                                                  \
    u64 f  = sub2(P, ii);                                                   \
    u64 p  = fma2(C3, f, C2);                                               \
    p = fma2(p, f, C1); p = fma2(p, f, ONE);                                \
    unsigned t0, t1, q0, q1;                                                \
    asm("mov.b64 {%0,%1},%2;" : "=r"(t0), "=r"(t1) : "l"(t));               \
    asm("mov.b64 {%0,%1},%2;" : "=r"(q0), "=r"(q1) : "l"(p));               \
    q0 += t0 << 23; q1 += t1 << 23;                                         \
    u64 e; asm("mov.b64 %0,{%1,%2};" : "=l"(e) : "r"(q0), "r"(q1));         \
    sep = add2(sep, e);                                                     \
} while (0)

// epilogue on saved (already merged) results c[8] with label pair lcp
#define EPILOGUE(c, lcp) do {                                               \
    u64 P0 = pk((lr0 != (lcp).x) ? (c)[0] : 0.f, (lr0 != (lcp).y) ? (c)[1] : 0.f); \
    u64 P1 = pk((lr1 != (lcp).x) ? (c)[2] : 0.f, (lr1 != (lcp).y) ? (c)[3] : 0.f); \
    u64 P2 = pk((lr2 != (lcp).x) ? (c)[4] : 0.f, (lr2 != (lcp).y) ? (c)[5] : 0.f); \
    u64 P3 = pk((lr3 != (lcp).x) ? (c)[6] : 0.f, (lr3 != (lcp).y) ? (c)[7] : 0.f); \
    sxp = add2(sxp, add2(add2(P0, P1), add2(P2, P3)));                      \
    EXP2ACC(sep0, P0);                                                      \
    EXP2ACC(sep1, P1);                                                      \
    EXP2ACC(sep2, P2);                                                      \
    EXP2ACC(sep3, P3);                                                      \
} while (0)

// ---------------- kernel 1: normalize z1/z2, compute pos (fp32), pack A fragments ----
__global__ void __launch_bounds__(256) k_norm_pack(const float* __restrict__ z1,
                                                   const float* __restrict__ z2) {
    if (blockIdx.x == 0 && blockIdx.y == 0 && threadIdx.x == 0) {
        g_acc = 0.0;
        g_tile = 0u;
    }
    const int b  = blockIdx.y;
    const int p0 = blockIdx.x * 32;
    const int tx = threadIdx.x & 31;   // pixel within tile
    const int ty = threadIdx.x >> 5;   // channel group

    __shared__ float s1[128][33];
    __shared__ float red[3][8][32];
    __shared__ float invsm[32];

    const float* z1b = z1 + (size_t)b * CDIM * NPIX + p0;
    const float* z2b = z2 + (size_t)b * CDIM * NPIX + p0;

    float ss1 = 0.f, ss2 = 0.f, dt = 0.f;
#pragma unroll
    for (int j = 0; j < 16; j++) {
        int c = ty * 16 + j;
        float v1 = z1b[(size_t)c * NPIX + tx];
        float v2 = z2b[(size_t)c * NPIX + tx];
        ss1 = fmaf(v1, v1, ss1);
        ss2 = fmaf(v2, v2, ss2);
        dt  = fmaf(v1, v2, dt);
        s1[c][tx] = v1;
    }
    red[0][ty][tx] = ss1; red[1][ty][tx] = ss2; red[2][ty][tx] = dt;
    __syncthreads();

    if (ty == 0) {
        float a = 0.f, bb = 0.f, d = 0.f;
#pragma unroll
        for (int j = 0; j < 8; j++) { a += red[0][j][tx]; bb += red[1][j][tx]; d += red[2][j][tx]; }
        float inv1 = 1.f / fmaxf(sqrtf(a),  1e-12f);
        float inv2 = 1.f / fmaxf(sqrtf(bb), 1e-12f);
        invsm[tx] = inv1;
        g_inv2 [b * NPIX + p0 + tx] = inv2;
        g_posl2[b * NPIX + p0 + tx] = d * inv1 * inv2 * SCALE_L2;  // pos in log2 domain
    }
    __syncthreads();

    // Pack A into mma fragment order
#pragma unroll
    for (int q = 0; q < 2; q++) {
        int wi   = threadIdx.x + q * 256;
        int rbl  = wi >> 8;
        int rem  = wi & 255;
        int s    = rem >> 5;
        int lane = rem & 31;
        int gid  = lane >> 2, tig = lane & 3;
        int pl   = rbl * 16 + gid;
        int k0   = s * 16 + tig * 2;
        float i1 = invsm[pl], i2 = invsm[pl + 8];
        uint4 o;
        o.x = pack2(s1[k0    ][pl]     * i1, s1[k0 + 1][pl]     * i1);
        o.y = pack2(s1[k0    ][pl + 8] * i2, s1[k0 + 1][pl + 8] * i2);
        o.z = pack2(s1[k0 + 8][pl]     * i1, s1[k0 + 9][pl]     * i1);
        o.w = pack2(s1[k0 + 8][pl + 8] * i2, s1[k0 + 9][pl + 8] * i2);
        int rb = blockIdx.x * 2 + rbl;
        g_Apack[((b * NROWBLK + rb) * 8 + s) * 32 + lane] = o;
    }
}

// ---------------- kernel 2: pack B fragments as uint4 (2 k-steps per entry) --------
__global__ void k_packB(const float* __restrict__ z2) {
    int g = blockIdx.x * 256 + threadIdx.x;       // 0..32767
    int b   = g >> 14;
    int r   = g & 16383;
    int it  = r >> 10;
    int idx = r & 1023;
    int nb  = idx >> 7;
    int s2  = (idx >> 5) & 3;
    int lane = idx & 31;
    int gid = lane >> 2, tig = lane & 3;
    int n  = nb * 8 + gid;
    int pq = LAST0 + it * 64 + n;
    float inv = g_inv2[b * NPIX + pq] * SCALE_L2;
    const float* zp = z2 + (size_t)b * CDIM * NPIX + pq;
    int k0 = s2 * 32 + tig * 2;
    uint4 o;
    o.x = pack2(zp[(size_t)(k0     ) * NPIX] * inv, zp[(size_t)(k0 +  1) * NPIX] * inv);
    o.y = pack2(zp[(size_t)(k0 +  8) * NPIX] * inv, zp[(size_t)(k0 +  9) * NPIX] * inv);
    o.z = pack2(zp[(size_t)(k0 + 16) * NPIX] * inv, zp[(size_t)(k0 + 17) * NPIX] * inv);
    o.w = pack2(zp[(size_t)(k0 + 24) * NPIX] * inv, zp[(size_t)(k0 + 25) * NPIX] * inv);
    g_Bpack[g] = o;
}

// ---------------- kernel 3: persistent bf16 GEMM (round-8 inner loop, no spills) ----
// 444 blocks (148 SMs x 3) x 128 threads. Tiles (b, 128 rows) from an atomic queue.
__global__ void __launch_bounds__(128, 3) k_main(const int* __restrict__ labels) {
    const int tid  = threadIdx.x;      // 0..127
    const int w    = tid >> 5;         // 0..3
    const int lane = tid & 31;
    const int gid  = lane >> 2, tig = lane & 3;

    __shared__ uint4    Bsm[2][1024];   // double-buffered 16KB B tiles
    __shared__ int      labsm[1024];
    __shared__ float    warpsum[4];
    __shared__ unsigned s_tile;

    // packed constants
    const u64 MAG = bc(12582912.0f);   // 1.5 * 2^23
    const u64 C3 = bc(5.5504108664e-2f);
    const u64 C2 = bc(2.4022650696e-1f);
    const u64 C1 = bc(6.9314718056e-1f);
    const u64 ONE = bc(1.0f);

    for (;;) {
        if (tid == 0) s_tile = atomicAdd(&g_tile, 1u);
        __syncthreads();
        const unsigned t = s_tile;
        if (t >= NTILES) break;
        const int b    = t >> 9;
        const int tloc = t & 511;
        const int row0 = tloc * 128;

        // labels of last chunk -> shared (visibility covered by it0's barrier)
        {
            const uint4* lp = (const uint4*)(labels + b * NPIX + LAST0);
            ((uint4*)labsm)[tid]       = lp[tid];
            ((uint4*)labsm)[tid + 128] = lp[tid + 128];
        }

        // A fragments for this warp's 32 rows (2 rowblocks): 16 x uint4
        const int rb0 = tloc * 8 + w * 2;
        uint4 a0[8], a1[8];
        const uint4* Ap = g_Apack + ((size_t)(b * NROWBLK + rb0) * 8) * 32 + lane;
#pragma unroll
        for (int s = 0; s < 8; s++) { a0[s] = Ap[s * 32]; a1[s] = Ap[256 + s * 32]; }

        const int r0  = row0 + w * 32 + gid;
        const int lr0 = labels[b * NPIX + r0];
        const int lr1 = labels[b * NPIX + r0 + 8];
        const int lr2 = labels[b * NPIX + r0 + 16];
        const int lr3 = labels[b * NPIX + r0 + 24];

        u64 sxp = 0;                                   // warp-global sum of masked logits
        u64 sep0 = 0, sep1 = 0, sep2 = 0, sep3 = 0;    // per-row-pair exp sums

        // 4 independent mma chains + pipelined saved results (round-8 structure)
        float eA0=0.f,eA1=0.f,eA2=0.f,eA3=0.f, oA0=0.f,oA1=0.f,oA2=0.f,oA3=0.f;
        float eB0=0.f,eB1=0.f,eB2=0.f,eB3=0.f, oB0=0.f,oB1=0.f,oB2=0.f,oB3=0.f;
        float csv[8];
        int2  lcp = make_int2(0, 0);

        const uint4* Bp = g_Bpack + b * 16384;

        // prefetch tile 0 (1024 uint4 by 128 threads)
        {
            unsigned sd = (unsigned)__cvta_generic_to_shared(&Bsm[0][0]);
#pragma unroll
            for (int i = 0; i < 8; i++)
                CP16(sd + (tid + 128 * i) * 16, Bp + tid + 128 * i);
            CPCOMMIT();
        }

        for (int it = 0; it < 16; it++) {
            const int buf = it & 1;
            CPWAIT0();
            __syncthreads();
            if (it < 15) {
                unsigned sd = (unsigned)__cvta_generic_to_shared(&Bsm[buf ^ 1][0]);
                const uint4* src = Bp + (it + 1) * 1024;
#pragma unroll
                for (int i = 0; i < 8; i++)
                    CP16(sd + (tid + 128 * i) * 16, src + tid + 128 * i);
                CPCOMMIT();
            }

            const uint4* Bb = &Bsm[buf][0];
#pragma unroll
            for (int nb = 0; nb < 8; nb++) {
                // (1) merge previous nb's chains into saved regs (results long ready)
                if (it + nb > 0) {
                    csv[0] = eA0 + oA0; csv[1] = eA1 + oA1;
                    csv[2] = eA2 + oA2; csv[3] = eA3 + oA3;
                    csv[4] = eB0 + oB0; csv[5] = eB1 + oB1;
                    csv[6] = eB2 + oB2; csv[7] = eB3 + oB3;
                }
                // (2) issue this nb's 16 mmas into the freed chains
                eA0=0.f;eA1=0.f;eA2=0.f;eA3=0.f; oA0=0.f;oA1=0.f;oA2=0.f;oA3=0.f;
                eB0=0.f;eB1=0.f;eB2=0.f;eB3=0.f; oB0=0.f;oB1=0.f;oB2=0.f;oB3=0.f;
#pragma unroll
                for (int s2 = 0; s2 < 4; s2++) {
                    uint4 bf = Bb[(nb * 4 + s2) * 32 + lane];
                    MMA_BF16(eA0, eA1, eA2, eA3, a0[2 * s2],     bf.x, bf.y);
                    MMA_BF16(eB0, eB1, eB2, eB3, a1[2 * s2],     bf.x, bf.y);
                    MMA_BF16(oA0, oA1, oA2, oA3, a0[2 * s2 + 1], bf.z, bf.w);
                    MMA_BF16(oB0, oB1, oB2, oB3, a1[2 * s2 + 1], bf.z, bf.w);
                }
                // (3) epilogue for the previous nb while these mmas are in flight
                if (it + nb > 0) EPILOGUE(csv, lcp);
                // (4) capture this nb's column labels for next round
                lcp = ((const int2*)labsm)[it * 32 + nb * 4 + tig];
            }
        }

        // drain: merge + epilogue for the final nb
        csv[0] = eA0 + oA0; csv[1] = eA1 + oA1;
        csv[2] = eA2 + oA2; csv[3] = eA3 + oA3;
        csv[4] = eB0 + oB0; csv[5] = eB1 + oB1;
        csv[6] = eB2 + oB2; csv[7] = eB3 + oB3;
        EPILOGUE(csv, lcp);

        // unpack packed accumulators
        float sa, sb;
        asm("mov.b64 {%0,%1},%2;" : "=f"(sa), "=f"(sb) : "l"(sxp));  float sxw = sa + sb;
        asm("mov.b64 {%0,%1},%2;" : "=f"(sa), "=f"(sb) : "l"(sep0)); float se0 = sa + sb;
        asm("mov.b64 {%0,%1},%2;" : "=f"(sa), "=f"(sb) : "l"(sep1)); float se1 = sa + sb;
        asm("mov.b64 {%0,%1},%2;" : "=f"(sa), "=f"(sb) : "l"(sep2)); float se2 = sa + sb;
        asm("mov.b64 {%0,%1},%2;" : "=f"(sa), "=f"(sb) : "l"(sep3)); float se3 = sa + sb;

        // per-row exp sums: reduce across the 4 lanes sharing each row
#pragma unroll
        for (int o = 1; o <= 2; o <<= 1) {
            se0 += __shfl_xor_sync(~0u, se0, o);
            se1 += __shfl_xor_sync(~0u, se1, o);
            se2 += __shfl_xor_sync(~0u, se2, o);
            se3 += __shfl_xor_sync(~0u, se3, o);
        }

        float v = 0.f;
        if (tig == 0) {
            float p0 = g_posl2[b * NPIX + r0];
            float p1 = g_posl2[b * NPIX + r0 + 8];
            float p2 = g_posl2[b * NPIX + r0 + 16];
            float p3 = g_posl2[b * NPIX + r0 + 24];
            float t0 = se0 + exp2p(p0);
            float t1 = se1 + exp2p(p1);
            float t2 = se2 + exp2p(p2);
            float t3 = se3 + exp2p(p3);
            v = (__log2f(t0) + __log2f(t1) + __log2f(t2) + __log2f(t3))
                - (p0 + p1 + p2 + p3) * (1.0f / 1025.0f);
        }
        v -= sxw * (1.0f / 1025.0f / 32.0f);   // spread warp-global sx over 32 lanes
#pragma unroll
        for (int o = 16; o; o >>= 1) v += __shfl_xor_sync(~0u, v, o);
        if (lane == 0) warpsum[w] = LN2F * v;
        __syncthreads();
        if (tid == 0) {
            float ts = warpsum[0] + warpsum[1] + warpsum[2] + warpsum[3];
            atomicAdd(&g_acc, (double)ts);
        }
        __syncthreads();   // warpsum consumed before next tile reuses it
    }
}

// ---------------- kernel 4: finalize ----------------
__global__ void k_finalize(float* out) {
    out[0] = (float)(g_acc / (double)(BATCH * NPIX));
}

// ---------------- launch ----------------
extern "C" void kernel_launch(void* const* d_in, const int* in_sizes, int n_in,
                              void* d_out, int out_size) {
    const float* z1     = (const float*)d_in[0];
    const float* z2     = (const float*)d_in[1];
    const int*   labels = (const int*)d_in[2];
    (void)in_sizes; (void)n_in; (void)out_size;

    dim3 g1(NPIX / 32, BATCH);
    k_norm_pack<<<g1, 256>>>(z1, z2);
    k_packB<<<128, 256>>>(z2);
    k_main<<<444, 128>>>(labels);
    k_finalize<<<1, 1>>>((float*)d_out);
}

// round 11
// speedup vs baseline: 1.0420x; 1.0126x over previous
#include <cuda_runtime.h>
#include <cuda_bf16.h>
#include <cstdint>

// Problem constants (fixed shapes)
#define BATCH 2
#define CDIM 128
#define NPIX 65536          // 256*256
#define LAST0 64512         // (chunks-1)*M
#define NROWBLK 4096        // NPIX/16
#define SCALE_L2 20.6099075f   // 1/(0.07 * ln2)
#define LN2F 0.6931471805599453f

typedef unsigned long long u64;

// ---------------- scratch (device globals: no allocations allowed) ----------
__device__ uint4    g_Apack[BATCH * NROWBLK * 8 * 32];   // 33.5 MB, bf16 mma A fragments
__device__ uint4    g_Bpack[BATCH * 16 * 1024];          // 512 KB: [b][it][(nb*4+s2)*32+lane]
__device__ float    g_posl2[BATCH * NPIX];               // pos logit in log2 domain
__device__ double   g_acc;
__device__ unsigned g_done;

// ---------------- helpers ----------------
__device__ __forceinline__ unsigned pack2(float lo, float hi) {
    __nv_bfloat162 h = __floats2bfloat162_rn(lo, hi);
    return *reinterpret_cast<unsigned*>(&h);
}
__device__ __forceinline__ u64 pk(float lo, float hi) {
    u64 r; asm("mov.b64 %0,{%1,%2};" : "=l"(r) : "f"(lo), "f"(hi)); return r;
}
__device__ __forceinline__ u64 bc(float x) {
    u64 r; asm("mov.b64 %0,{%1,%1};" : "=l"(r) : "f"(x)); return r;
}
__device__ __forceinline__ u64 fma2(u64 a, u64 b, u64 c) {
    u64 d; asm("fma.rn.f32x2 %0,%1,%2,%3;" : "=l"(d) : "l"(a), "l"(b), "l"(c)); return d;
}
__device__ __forceinline__ u64 add2(u64 a, u64 b) {
    u64 d; asm("add.rn.f32x2 %0,%1,%2;" : "=l"(d) : "l"(a), "l"(b)); return d;
}
__device__ __forceinline__ u64 sub2(u64 a, u64 b) {
    u64 d; asm("sub.rn.f32x2 %0,%1,%2;" : "=l"(d) : "l"(a), "l"(b)); return d;
}
// scalar exp2 (pos only). Exact at x==0.
__device__ __forceinline__ float exp2p(float x) {
    int   i = __float2int_rn(x);
    float f = x - (float)i;
    float p = 9.6181291076e-3f;
    p = fmaf(p, f, 5.5504108664e-2f);
    p = fmaf(p, f, 2.4022650696e-1f);
    p = fmaf(p, f, 6.9314718056e-1f);
    p = fmaf(p, f, 1.0f);
    return __int_as_float(__float_as_int(p) + (i << 23));
}

#define CP16(dst, src) asm volatile("cp.async.ca.shared.global [%0],[%1],16;\n" :: "r"(dst), "l"(src))
#define CPCOMMIT()     asm volatile("cp.async.commit_group;\n")
#define CPWAIT0()      asm volatile("cp.async.wait_group 0;\n")

#define MMA_BF16(c0, c1, c2, c3, av, b0, b1)                               \
    asm volatile(                                                           \
        "mma.sync.aligned.m16n8k16.row.col.f32.bf16.bf16.f32 "             \
        "{%0,%1,%2,%3}, {%4,%5,%6,%7}, {%8,%9}, {%0,%1,%2,%3};\n"          \
        : "+f"(c0), "+f"(c1), "+f"(c2), "+f"(c3)                            \
        : "r"((av).x), "r"((av).y), "r"((av).z), "r"((av).w),               \
          "r"(b0), "r"(b1))

// packed exp2 accumulate: sep += exp2(P) elementwise (deg-3 Taylor, exact at 0)
#define EXP2ACC(sep, P) do {                                                \
    u64 t  = add2(P, MAG);                                                  \
    u64 ii = sub2(t, MAG);                                                  \
    u64 f  = sub2(P, ii);                                                   \
    u64 p  = fma2(C3, f, C2);                                               \
    p = fma2(p, f, C1); p = fma2(p, f, ONE);                                \
    unsigned t0, t1, q0, q1;                                                \
    asm("mov.b64 {%0,%1},%2;" : "=r"(t0), "=r"(t1) : "l"(t));               \
    asm("mov.b64 {%0,%1},%2;" : "=r"(q0), "=r"(q1) : "l"(p));               \
    q0 += t0 << 23; q1 += t1 << 23;                                         \
    u64 e; asm("mov.b64 %0,{%1,%2};" : "=l"(e) : "r"(q0), "r"(q1));         \
    sep = add2(sep, e);                                                     \
} while (0)

// epilogue on saved (already merged) results c[8] with label pair lcp
#define EPILOGUE(c, lcp) do {                                               \
    u64 P0 = pk((lr0 != (lcp).x) ? (c)[0] : 0.f, (lr0 != (lcp).y) ? (c)[1] : 0.f); \
    u64 P1 = pk((lr1 != (lcp).x) ? (c)[2] : 0.f, (lr1 != (lcp).y) ? (c)[3] : 0.f); \
    u64 P2 = pk((lr2 != (lcp).x) ? (c)[4] : 0.f, (lr2 != (lcp).y) ? (c)[5] : 0.f); \
    u64 P3 = pk((lr3 != (lcp).x) ? (c)[6] : 0.f, (lr3 != (lcp).y) ? (c)[7] : 0.f); \
    sxp = add2(sxp, add2(add2(P0, P1), add2(P2, P3)));                      \
    EXP2ACC(sep0, P0);                                                      \
    EXP2ACC(sep1, P1);                                                      \
    EXP2ACC(sep2, P2);                                                      \
    EXP2ACC(sep3, P3);                                                      \
} while (0)

// ---------------- kernel 1: normalize, pos, pack A fragments, pack B (last chunk) ---
__global__ void __launch_bounds__(256) k_norm_pack(const float* __restrict__ z1,
                                                   const float* __restrict__ z2) {
    if (blockIdx.x == 0 && blockIdx.y == 0 && threadIdx.x == 0) {
        g_acc = 0.0;
        g_done = 0u;
    }
    const int b  = blockIdx.y;
    const int p0 = blockIdx.x * 32;
    const int tx = threadIdx.x & 31;   // pixel within tile
    const int ty = threadIdx.x >> 5;   // channel group

    __shared__ float s1[128][33];
    __shared__ float s2m[128][33];
    __shared__ float red[3][8][32];
    __shared__ float invsm[32];
    __shared__ float inv2sm[32];

    const float* z1b = z1 + (size_t)b * CDIM * NPIX + p0;
    const float* z2b = z2 + (size_t)b * CDIM * NPIX + p0;

    float ss1 = 0.f, ss2 = 0.f, dt = 0.f;
#pragma unroll
    for (int j = 0; j < 16; j++) {
        int c = ty * 16 + j;
        float v1 = z1b[(size_t)c * NPIX + tx];
        float v2 = z2b[(size_t)c * NPIX + tx];
        ss1 = fmaf(v1, v1, ss1);
        ss2 = fmaf(v2, v2, ss2);
        dt  = fmaf(v1, v2, dt);
        s1[c][tx]  = v1;
        s2m[c][tx] = v2;
    }
    red[0][ty][tx] = ss1; red[1][ty][tx] = ss2; red[2][ty][tx] = dt;
    __syncthreads();

    if (ty == 0) {
        float a = 0.f, bb = 0.f, d = 0.f;
#pragma unroll
        for (int j = 0; j < 8; j++) { a += red[0][j][tx]; bb += red[1][j][tx]; d += red[2][j][tx]; }
        float inv1 = 1.f / fmaxf(sqrtf(a),  1e-12f);
        float inv2 = 1.f / fmaxf(sqrtf(bb), 1e-12f);
        invsm[tx]  = inv1;
        inv2sm[tx] = inv2;
        g_posl2[b * NPIX + p0 + tx] = d * inv1 * inv2 * SCALE_L2;  // pos in log2 domain
    }
    __syncthreads();

    // Pack A into mma fragment order
#pragma unroll
    for (int q = 0; q < 2; q++) {
        int wi   = threadIdx.x + q * 256;
        int rbl  = wi >> 8;
        int rem  = wi & 255;
        int s    = rem >> 5;
        int lane = rem & 31;
        int gid  = lane >> 2, tig = lane & 3;
        int pl   = rbl * 16 + gid;
        int k0   = s * 16 + tig * 2;
        float i1 = invsm[pl], i2 = invsm[pl + 8];
        uint4 o;
        o.x = pack2(s1[k0    ][pl]     * i1, s1[k0 + 1][pl]     * i1);
        o.y = pack2(s1[k0    ][pl + 8] * i2, s1[k0 + 1][pl + 8] * i2);
        o.z = pack2(s1[k0 + 8][pl]     * i1, s1[k0 + 9][pl]     * i1);
        o.w = pack2(s1[k0 + 8][pl + 8] * i2, s1[k0 + 9][pl + 8] * i2);
        int rb = blockIdx.x * 2 + rbl;
        g_Apack[((b * NROWBLK + rb) * 8 + s) * 32 + lane] = o;
    }

    // Pack B fragments (only blocks covering the last chunk: 32 of 2048)
    if (p0 >= LAST0) {
        int idx = threadIdx.x;
        int cl  = idx >> 3;              // local col 0..31
        int sub = idx & 7;               // 8 subtasks/col
        int s2v = sub & 3;               // k-step pair 0..3
        int tg0 = (sub >> 2) << 1;       // tig base: 0 or 2
        int col = (p0 - LAST0) + cl;     // 0..1023
        int it  = col >> 6;
        int nb  = (col >> 3) & 7;
        int gid = col & 7;
        float inv = inv2sm[cl] * SCALE_L2;
#pragma unroll
        for (int d2 = 0; d2 < 2; d2++) {
            int tig = tg0 + d2;
            int k0  = s2v * 32 + tig * 2;
            uint4 o;
            o.x = pack2(s2m[k0     ][cl] * inv, s2m[k0 +  1][cl] * inv);
            o.y = pack2(s2m[k0 +  8][cl] * inv, s2m[k0 +  9][cl] * inv);
            o.z = pack2(s2m[k0 + 16][cl] * inv, s2m[k0 + 17][cl] * inv);
            o.w = pack2(s2m[k0 + 24][cl] * inv, s2m[k0 + 25][cl] * inv);
            g_Bpack[(b * 16 + it) * 1024 + (nb * 4 + s2v) * 32 + gid * 4 + tig] = o;
        }
    }
}

// ---------------- kernel 2: bf16 GEMM + fused epilogue + folded finalize ------------
__global__ void __launch_bounds__(128, 3) k_main(const int* __restrict__ labels,
                                                 float* __restrict__ out) {
    const int b    = blockIdx.y;
    const int row0 = blockIdx.x * 128;
    const int tid  = threadIdx.x;      // 0..127
    const int w    = tid >> 5;         // 0..3
    const int lane = tid & 31;
    const int gid  = lane >> 2, tig = lane & 3;

    __shared__ uint4 Bsm[2][1024];   // double-buffered 16KB B tiles
    __shared__ int   labsm[1024];
    __shared__ float warpsum[4];

    // labels of last chunk -> shared (vectorized, 128 threads x 2)
    {
        const uint4* lp = (const uint4*)(labels + b * NPIX + LAST0);
        ((uint4*)labsm)[tid]       = lp[tid];
        ((uint4*)labsm)[tid + 128] = lp[tid + 128];
    }

    // A fragments for this warp's 32 rows (2 rowblocks): 16 x uint4
    const int rb0 = blockIdx.x * 8 + w * 2;
    uint4 a0[8], a1[8];
    const uint4* Ap = g_Apack + ((size_t)(b * NROWBLK + rb0) * 8) * 32 + lane;
#pragma unroll
    for (int s = 0; s < 8; s++) { a0[s] = Ap[s * 32]; a1[s] = Ap[256 + s * 32]; }

    const int r0  = row0 + w * 32 + gid;
    const int lr0 = labels[b * NPIX + r0];
    const int lr1 = labels[b * NPIX + r0 + 8];
    const int lr2 = labels[b * NPIX + r0 + 16];
    const int lr3 = labels[b * NPIX + r0 + 24];

    // packed constants
    const u64 MAG = bc(12582912.0f);   // 1.5 * 2^23
    const u64 C3 = bc(5.5504108664e-2f);
    const u64 C2 = bc(2.4022650696e-1f);
    const u64 C1 = bc(6.9314718056e-1f);
    const u64 ONE = bc(1.0f);

    u64 sxp = 0;                                   // warp-global sum of masked logits
    u64 sep0 = 0, sep1 = 0, sep2 = 0, sep3 = 0;    // per-row-pair exp sums

    // 4 independent mma chains + pipelined saved results
    float eA0=0.f,eA1=0.f,eA2=0.f,eA3=0.f, oA0=0.f,oA1=0.f,oA2=0.f,oA3=0.f;
    float eB0=0.f,eB1=0.f,eB2=0.f,eB3=0.f, oB0=0.f,oB1=0.f,oB2=0.f,oB3=0.f;
    float csv[8];
    int2  lcp = make_int2(0, 0);

    const uint4* Bp = g_Bpack + b * 16384;

    // prefetch tile 0 (1024 uint4 by 128 threads)
    {
        unsigned sd = (unsigned)__cvta_generic_to_shared(&Bsm[0][0]);
#pragma unroll
        for (int i = 0; i < 8; i++)
            CP16(sd + (tid + 128 * i) * 16, Bp + tid + 128 * i);
        CPCOMMIT();
    }

    for (int it = 0; it < 16; it++) {
        const int buf = it & 1;
        CPWAIT0();
        __syncthreads();
        if (it < 15) {
            unsigned sd = (unsigned)__cvta_generic_to_shared(&Bsm[buf ^ 1][0]);
            const uint4* src = Bp + (it + 1) * 1024;
#pragma unroll
            for (int i = 0; i < 8; i++)
                CP16(sd + (tid + 128 * i) * 16, src + tid + 128 * i);
            CPCOMMIT();
        }

        const uint4* Bb = &Bsm[buf][0];
        uint4 bf = Bb[lane];   // register prefetch of B fragment group j=0
#pragma unroll
        for (int nb = 0; nb < 8; nb++) {
            // (1) merge previous nb's chains into saved regs (results long ready)
            if (it + nb > 0) {
                csv[0] = eA0 + oA0; csv[1] = eA1 + oA1;
                csv[2] = eA2 + oA2; csv[3] = eA3 + oA3;
                csv[4] = eB0 + oB0; csv[5] = eB1 + oB1;
                csv[6] = eB2 + oB2; csv[7] = eB3 + oB3;
            }
            // (2) issue this nb's 16 mmas, prefetching the next B fragment group
            eA0=0.f;eA1=0.f;eA2=0.f;eA3=0.f; oA0=0.f;oA1=0.f;oA2=0.f;oA3=0.f;
            eB0=0.f;eB1=0.f;eB2=0.f;eB3=0.f; oB0=0.f;oB1=0.f;oB2=0.f;oB3=0.f;
#pragma unroll
            for (int s2 = 0; s2 < 4; s2++) {
                uint4 bcur = bf;
                if (nb * 4 + s2 < 31)
                    bf = Bb[(nb * 4 + s2 + 1) * 32 + lane];
                MMA_BF16(eA0, eA1, eA2, eA3, a0[2 * s2],     bcur.x, bcur.y);
                MMA_BF16(eB0, eB1, eB2, eB3, a1[2 * s2],     bcur.x, bcur.y);
                MMA_BF16(oA0, oA1, oA2, oA3, a0[2 * s2 + 1], bcur.z, bcur.w);
                MMA_BF16(oB0, oB1, oB2, oB3, a1[2 * s2 + 1], bcur.z, bcur.w);
            }
            // (3) epilogue for the previous nb while these mmas are in flight
            if (it + nb > 0) EPILOGUE(csv, lcp);
            // (4) capture this nb's column labels for next round
            lcp = ((const int2*)labsm)[it * 32 + nb * 4 + tig];
        }
        __syncthreads();   // all reads of buf done before next prefetch overwrites
    }

    // drain: merge + epilogue for the final nb
    csv[0] = eA0 + oA0; csv[1] = eA1 + oA1;
    csv[2] = eA2 + oA2; csv[3] = eA3 + oA3;
    csv[4] = eB0 + oB0; csv[5] = eB1 + oB1;
    csv[6] = eB2 + oB2; csv[7] = eB3 + oB3;
    EPILOGUE(csv, lcp);

    // unpack packed accumulators
    float sa, sb;
    asm("mov.b64 {%0,%1},%2;" : "=f"(sa), "=f"(sb) : "l"(sxp));  float sxw = sa + sb;
    asm("mov.b64 {%0,%1},%2;" : "=f"(sa), "=f"(sb) : "l"(sep0)); float se0 = sa + sb;
    asm("mov.b64 {%0,%1},%2;" : "=f"(sa), "=f"(sb) : "l"(sep1)); float se1 = sa + sb;
    asm("mov.b64 {%0,%1},%2;" : "=f"(sa), "=f"(sb) : "l"(sep2)); float se2 = sa + sb;
    asm("mov.b64 {%0,%1},%2;" : "=f"(sa), "=f"(sb) : "l"(sep3)); float se3 = sa + sb;

    // per-row exp sums: reduce across the 4 lanes sharing each row
#pragma unroll
    for (int o = 1; o <= 2; o <<= 1) {
        se0 += __shfl_xor_sync(~0u, se0, o);
        se1 += __shfl_xor_sync(~0u, se1, o);
        se2 += __shfl_xor_sync(~0u, se2, o);
        se3 += __shfl_xor_sync(~0u, se3, o);
    }

    float v = 0.f;
    if (tig == 0) {
        float p0 = g_posl2[b * NPIX + r0];
        float p1 = g_posl2[b * NPIX + r0 + 8];
        float p2 = g_posl2[b * NPIX + r0 + 16];
        float p3 = g_posl2[b * NPIX + r0 + 24];
        float t0 = se0 + exp2p(p0);
        float t1 = se1 + exp2p(p1);
        float t2 = se2 + exp2p(p2);
        float t3 = se3 + exp2p(p3);
        v = (__log2f(t0) + __log2f(t1) + __log2f(t2) + __log2f(t3))
            - (p0 + p1 + p2 + p3) * (1.0f / 1025.0f);
    }
    v -= sxw * (1.0f / 1025.0f / 32.0f);   // spread warp-global sx over 32 lanes
#pragma unroll
    for (int o = 16; o; o >>= 1) v += __shfl_xor_sync(~0u, v, o);
    if (lane == 0) warpsum[w] = LN2F * v;
    __syncthreads();
    if (tid == 0) {
        float ts = warpsum[0] + warpsum[1] + warpsum[2] + warpsum[3];
        atomicAdd(&g_acc, (double)ts);
        __threadfence();
        unsigned done = atomicAdd(&g_done, 1u) + 1u;
        if (done == gridDim.x * gridDim.y) {
            double total = atomicAdd(&g_acc, 0.0);   // coherent read after all adds
            out[0] = (float)(total / (double)(BATCH * NPIX));
        }
    }
}

// ---------------- launch ----------------
extern "C" void kernel_launch(void* const* d_in, const int* in_sizes, int n_in,
                              void* d_out, int out_size) {
    const float* z1     = (const float*)d_in[0];
    const float* z2     = (const float*)d_in[1];
    const int*   labels = (const int*)d_in[2];
    (void)in_sizes; (void)n_in; (void)out_size;

    dim3 g1(NPIX / 32, BATCH);
    k_norm_pack<<<g1, 256>>>(z1, z2);
    dim3 g2(NPIX / 128, BATCH);
    k_main<<<g2, 128>>>(labels, (float*)d_out);
}